// round 3
// baseline (speedup 1.0000x reference)
#include <cuda_runtime.h>

#define BB 64
#define HH 512
#define LL 128
#define GRID 128
#define TPB 256

// persistent state
__device__ float g_ctx[(size_t)BB * LL * HH];  // [b][l][h]
__device__ float g_h[BB * HH];
__device__ float g_c[BB * HH];
__device__ float g_cat[BB * 2 * HH];           // [b][0:512]=hid, [512:1024]=h_t
__device__ float g_inp[BB * HH];
__device__ float g_mask[BB * LL];

// grid barrier state
__device__ unsigned g_cnt;
__device__ volatile unsigned g_rel;

#define OUT_PTR  (BB * LL * LL)
#define OUT_H    (OUT_PTR + BB * LL)
#define OUT_C    (OUT_H + BB * HH)

__device__ __forceinline__ float wsum(float v) {
#pragma unroll
    for (int off = 16; off; off >>= 1) v += __shfl_xor_sync(0xffffffffu, v, off);
    return v;
}

// fast tanh for attention scores: abs err ~1e-7, handles +-inf saturation
__device__ __forceinline__ float fast_tanh(float x) {
    float e = __expf(2.0f * x);
    return 1.0f - __fdividef(2.0f, e + 1.0f);
}

// epoch grid barrier (all GRID blocks participate every call)
__device__ __forceinline__ void gbar(unsigned e) {
    __syncthreads();
    if (threadIdx.x == 0) {
        __threadfence();  // publish this block's writes
        unsigned a = atomicAdd(&g_cnt, 1u) + 1u;
        if (a == e * GRID) {
            g_rel = e;
        } else {
            while (g_rel < e) { __nanosleep(40); }
        }
        __threadfence();  // acquire: invalidate L1 so post-barrier loads are fresh
    }
    __syncthreads();
}

// ---------------- init ----------------
__global__ void k_init(const float* __restrict__ h0, const float* __restrict__ c0) {
    int i = blockIdx.x * blockDim.x + threadIdx.x;
    if (i < BB * HH) { g_h[i] = h0[i]; g_c[i] = c0[i]; }
    if (i < BB * LL) g_mask[i] = 1.0f;
    if (i == 0) { g_cnt = 0u; g_rel = 0u; }
}

// ---------------- ctx precompute (unchanged from R0, proven correct) ----------------
__global__ __launch_bounds__(256) void k_ctx(const float* __restrict__ Wc,
                                             const float* __restrict__ bc,
                                             const float* __restrict__ ctxin) {
    __shared__ float s_in[256][36];
    int b = blockIdx.x;
    int l0 = blockIdx.y * 32;
    int tid = threadIdx.x;
    int h0i = tid, h1i = tid + 256;

    float acc0[32], acc1[32];
    float bc0 = bc[h0i], bc1 = bc[h1i];
#pragma unroll
    for (int l = 0; l < 32; l++) { acc0[l] = bc0; acc1[l] = bc1; }

    for (int dc = 0; dc < HH; dc += 256) {
        __syncthreads();
        const float* src = ctxin + ((size_t)b * HH + dc + tid) * LL + l0;
#pragma unroll
        for (int l = 0; l < 32; l += 4) {
            float4 v = *reinterpret_cast<const float4*>(src + l);
            *reinterpret_cast<float4*>(&s_in[tid][l]) = v;
        }
        __syncthreads();

        const float* w0 = Wc + (size_t)h0i * HH + dc;
        const float* w1 = Wc + (size_t)h1i * HH + dc;
        for (int d4 = 0; d4 < 256; d4 += 4) {
            float4 wa = *reinterpret_cast<const float4*>(w0 + d4);
            float4 wb = *reinterpret_cast<const float4*>(w1 + d4);
            float wav[4] = {wa.x, wa.y, wa.z, wa.w};
            float wbv[4] = {wb.x, wb.y, wb.z, wb.w};
#pragma unroll
            for (int dd = 0; dd < 4; dd++) {
                float a = wav[dd], bw = wbv[dd];
#pragma unroll
                for (int l = 0; l < 32; l += 4) {
                    float4 s = *reinterpret_cast<const float4*>(&s_in[d4 + dd][l]);
                    acc0[l + 0] += a * s.x; acc0[l + 1] += a * s.y;
                    acc0[l + 2] += a * s.z; acc0[l + 3] += a * s.w;
                    acc1[l + 0] += bw * s.x; acc1[l + 1] += bw * s.y;
                    acc1[l + 2] += bw * s.z; acc1[l + 3] += bw * s.w;
                }
            }
        }
    }
#pragma unroll
    for (int l = 0; l < 32; l++) {
        size_t base = ((size_t)b * LL + l0 + l) * HH;
        g_ctx[base + h0i] = acc0[l];
        g_ctx[base + h1i] = acc1[l];
    }
}

// ---------------- linear phase (device func): out[b,r] = epi(W x + bias) ----------------
template <int KDIM, int EPI_TANH>
__device__ __forceinline__ void lin_phase(float (*xs)[512],
                                          const float* __restrict__ W,
                                          const float* __restrict__ bias,
                                          const float* __restrict__ xbase, int xstride,
                                          float* __restrict__ outp, int ostride,
                                          int blk, int tid) {
    int lane = tid & 31, wi = tid >> 5;
    int rbase = (blk & 31) * 16;
    int bbase = (blk >> 5) * 16;
    int r0 = rbase + wi * 2;

    float acc[2][16];
#pragma unroll
    for (int r = 0; r < 2; r++)
#pragma unroll
        for (int b = 0; b < 16; b++) acc[r][b] = 0.f;

    for (int kc = 0; kc < KDIM; kc += 512) {
        __syncthreads();
        for (int idx = tid; idx < 16 * 512; idx += TPB) {
            int b = idx >> 9, k = idx & 511;
            xs[b][k] = xbase[(size_t)(bbase + b) * xstride + kc + k];
        }
        __syncthreads();
        const float* w0 = W + (size_t)r0 * KDIM + kc;
        const float* w1 = W + (size_t)(r0 + 1) * KDIM + kc;
        float a0 = w0[lane], a1 = w1[lane];
        for (int kk = 0; kk < 16; kk++) {
            float na0 = 0.f, na1 = 0.f;
            if (kk < 15) {
                int kn = (kk + 1) * 32 + lane;
                na0 = w0[kn]; na1 = w1[kn];
            }
            int k = kk * 32 + lane;
#pragma unroll
            for (int b = 0; b < 16; b++) {
                float xv = xs[b][k];
                acc[0][b] += a0 * xv;
                acc[1][b] += a1 * xv;
            }
            a0 = na0; a1 = na1;
        }
    }

    float res[2] = {0.f, 0.f};
#pragma unroll
    for (int r = 0; r < 2; r++)
#pragma unroll
        for (int b = 0; b < 16; b++) {
            float v = wsum(acc[r][b]);
            if (lane == b) res[r] = v;
        }

    if (lane < 16) {
        int b = bbase + lane;
#pragma unroll
        for (int r = 0; r < 2; r++) {
            float v = res[r] + bias[r0 + r];
            if (EPI_TANH) v = tanhf(v);
            outp[(size_t)b * ostride + r0 + r] = v;
        }
    }
}

// ---------------- the persistent step kernel ----------------
__global__ __launch_bounds__(TPB, 1) void k_steps(
    const float* __restrict__ Whh, const float* __restrict__ bhh,
    const float* __restrict__ Win, const float* __restrict__ bin,
    const float* __restrict__ Wout, const float* __restrict__ bout,
    const float* __restrict__ V, float* __restrict__ out) {
    __shared__ float xs[16][512];   // GEMM staging (32KB)
    __shared__ float inp_s[HH];
    __shared__ float sc_s[LL];
    __shared__ float alpha_s[LL];
    __shared__ float mask_s[LL];

    const int blk = blockIdx.x;
    const int tid = threadIdx.x, lane = tid & 31, w = tid >> 5;
    unsigned ep = 0;

    for (int t = 0; t < LL; t++) {
        // ======== Phase A: gates GEMM + LSTM cell (256 vtiles, 2 per block) ========
        for (int v = blk; v < 256; v += GRID) {
            int it = v & 63, bt = v >> 6;
            int bbase = bt * 16, ibase = it * 8;
            __syncthreads();
            for (int idx = tid; idx < 16 * 512; idx += TPB) {
                int b = idx >> 9, k = idx & 511;
                xs[b][k] = g_h[(bbase + b) * HH + k];
            }
            __syncthreads();

            int i = ibase + w;
            const float* wr0 = Whh + (size_t)(0 * HH + i) * HH;
            const float* wr1 = Whh + (size_t)(1 * HH + i) * HH;
            const float* wr2 = Whh + (size_t)(2 * HH + i) * HH;
            const float* wr3 = Whh + (size_t)(3 * HH + i) * HH;

            float acc[4][16];
#pragma unroll
            for (int g = 0; g < 4; g++)
#pragma unroll
                for (int b = 0; b < 16; b++) acc[g][b] = 0.f;

            float c0 = wr0[lane], c1 = wr1[lane], c2 = wr2[lane], c3 = wr3[lane];
            for (int kk = 0; kk < 16; kk++) {
                float n0 = 0.f, n1 = 0.f, n2 = 0.f, n3 = 0.f;
                if (kk < 15) {
                    int kn = (kk + 1) * 32 + lane;
                    n0 = wr0[kn]; n1 = wr1[kn]; n2 = wr2[kn]; n3 = wr3[kn];
                }
                int k = kk * 32 + lane;
#pragma unroll
                for (int b = 0; b < 16; b++) {
                    float hv = xs[b][k];
                    acc[0][b] += c0 * hv;
                    acc[1][b] += c1 * hv;
                    acc[2][b] += c2 * hv;
                    acc[3][b] += c3 * hv;
                }
                c0 = n0; c1 = n1; c2 = n2; c3 = n3;
            }

            float gate[4] = {0.f, 0.f, 0.f, 0.f};
#pragma unroll
            for (int g = 0; g < 4; g++)
#pragma unroll
                for (int b = 0; b < 16; b++) {
                    float vv = wsum(acc[g][b]);
                    if (lane == b) gate[g] = vv;
                }

            if (lane < 16) {
                int b = bbase + lane;
                float ig = gate[0] + bhh[0 * HH + i];
                float fg = gate[1] + bhh[1 * HH + i];
                float gg = gate[2] + bhh[2 * HH + i];
                float og = gate[3] + bhh[3 * HH + i];
                float c_old = g_c[b * HH + i];
                float si = 1.f / (1.f + expf(-ig));
                float sf = 1.f / (1.f + expf(-fg));
                float so = 1.f / (1.f + expf(-og));
                float ct = sf * c_old + si * tanhf(gg);
                float ht = so * tanhf(ct);
                g_c[b * HH + i] = ct;
                g_cat[b * 2 * HH + HH + i] = ht;
            }
        }
        gbar(++ep);

        // ======== Phase B: inp = W_in * h_t + b_in ========
        lin_phase<512, 0>(xs, Win, bin, (const float*)g_cat + HH, 2 * HH,
                          g_inp, HH, blk, tid);
        gbar(++ep);

        // ======== Phase C: attention (blocks 0..63, one batch each) ========
        if (blk < BB) {
            int b = blk;
            inp_s[tid] = g_inp[b * HH + tid];
            inp_s[tid + 256] = g_inp[b * HH + tid + 256];
            if (tid < LL) mask_s[tid] = g_mask[b * LL + tid];
            __syncthreads();

            float inpv[16], Vv[16];
#pragma unroll
            for (int m = 0; m < 16; m++) {
                inpv[m] = inp_s[m * 32 + lane];
                Vv[m] = V[m * 32 + lane];
            }

            // scores: 8 warps x 16 l
            for (int li = 0; li < 16; li++) {
                int l = w * 16 + li;
                const float* cp = g_ctx + ((size_t)b * LL + l) * HH + lane;
                float s = 0.f;
#pragma unroll
                for (int m = 0; m < 16; m++) {
                    float cv = cp[m * 32];
                    s += Vv[m] * fast_tanh(inpv[m] + cv);
                }
                s = wsum(s);
                if (lane == 0) sc_s[l] = s;
            }
            __syncthreads();

            if (w == 0) {
                float sv[4], mk[4];
#pragma unroll
                for (int j = 0; j < 4; j++) {
                    mk[j] = mask_s[lane + 32 * j];
                    sv[j] = (mk[j] != 0.f) ? sc_s[lane + 32 * j] : -3.4e38f;
                }
                float m = fmaxf(fmaxf(sv[0], sv[1]), fmaxf(sv[2], sv[3]));
#pragma unroll
                for (int off = 16; off; off >>= 1)
                    m = fmaxf(m, __shfl_xor_sync(0xffffffffu, m, off));

                float e[4], sum = 0.f;
#pragma unroll
                for (int j = 0; j < 4; j++) {
                    e[j] = (mk[j] != 0.f) ? expf(sv[j] - m) : 0.f;
                    sum += e[j];
                }
                sum = wsum(sum);
                float inv = 1.f / sum;

                float best = -1.f;
                int bidx = 0;
#pragma unroll
                for (int j = 0; j < 4; j++) {
                    int l = lane + 32 * j;
                    float a = e[j] * inv;
                    alpha_s[l] = a;
                    out[(size_t)b * LL * LL + (size_t)t * LL + l] = a;
                    float cand = (mk[j] != 0.f) ? a : -1.f;
                    if (cand > best) { best = cand; bidx = l; }
                }
#pragma unroll
                for (int off = 16; off; off >>= 1) {
                    float ob = __shfl_xor_sync(0xffffffffu, best, off);
                    int oi = __shfl_xor_sync(0xffffffffu, bidx, off);
                    if (ob > best || (ob == best && oi < bidx)) { best = ob; bidx = oi; }
                }
                if (lane == 0) {
                    out[OUT_PTR + b * LL + t] = (float)bidx;
                    g_mask[b * LL + bidx] = 0.f;
                }
            }
            __syncthreads();

            // hid[h] = sum_l ctx[b,l,h] * alpha[l]
            for (int hh = tid; hh < HH; hh += TPB) {
                float a = 0.f;
                const float* cp = g_ctx + (size_t)b * LL * HH + hh;
#pragma unroll 8
                for (int l = 0; l < LL; l++) a += cp[(size_t)l * HH] * alpha_s[l];
                g_cat[b * 2 * HH + hh] = a;
            }
        }
        gbar(++ep);

        // ======== Phase D: h = tanh(W_out * [hid, h_t] + b_out) ========
        lin_phase<1024, 1>(xs, Wout, bout, (const float*)g_cat, 2 * HH,
                           g_h, HH, blk, tid);
        gbar(++ep);
    }

    // final h/c copy
    for (int i = blk * TPB + tid; i < BB * HH; i += GRID * TPB) {
        out[OUT_H + i] = g_h[i];
        out[OUT_C + i] = g_c[i];
    }
}

extern "C" void kernel_launch(void* const* d_in, const int* in_sizes, int n_in,
                              void* d_out, int out_size) {
    const float* h0   = (const float*)d_in[2];
    const float* c0   = (const float*)d_in[3];
    const float* ctxi = (const float*)d_in[4];
    const float* Whh  = (const float*)d_in[5];
    const float* bhh  = (const float*)d_in[6];
    const float* Win  = (const float*)d_in[7];
    const float* bin  = (const float*)d_in[8];
    const float* Wc   = (const float*)d_in[9];
    const float* bc   = (const float*)d_in[10];
    const float* V    = (const float*)d_in[11];
    const float* Wout = (const float*)d_in[12];
    const float* bout = (const float*)d_in[13];
    float* out = (float*)d_out;

    k_init<<<(BB * HH + 255) / 256, 256>>>(h0, c0);
    k_ctx<<<dim3(BB, LL / 32), 256>>>(Wc, bc, ctxi);
    k_steps<<<GRID, TPB>>>(Whh, bhh, Win, bin, Wout, bout, V, out);
}

// round 4
// speedup vs baseline: 1.4347x; 1.4347x over previous
#include <cuda_runtime.h>

#define BB 64
#define HH 512
#define LL 128
#define GRID 128
#define TPB 512

// persistent state
__device__ float g_ctx[(size_t)BB * LL * HH];  // [b][l][h]
__device__ float g_h[BB * HH];
__device__ float g_c[BB * HH];
__device__ float g_cat[BB * 2 * HH];           // [b][0:512]=hid, [512:1024]=h_t
__device__ float g_inp[BB * HH];
__device__ float g_mask[BB * LL];
__device__ float g_sc[BB * LL];
__device__ int   g_bidx[BB];

// grid barrier state
__device__ unsigned g_cnt;
__device__ volatile unsigned g_rel;

#define OUT_PTR  (BB * LL * LL)
#define OUT_H    (OUT_PTR + BB * LL)
#define OUT_C    (OUT_H + BB * HH)

__device__ __forceinline__ float wsum(float v) {
#pragma unroll
    for (int off = 16; off; off >>= 1) v += __shfl_xor_sync(0xffffffffu, v, off);
    return v;
}

// fast tanh for attention scores: abs err ~1e-7, saturates correctly
__device__ __forceinline__ float fast_tanh(float x) {
    float e = __expf(2.0f * x);
    return 1.0f - __fdividef(2.0f, e + 1.0f);
}

// epoch grid barrier (all GRID blocks participate every call)
__device__ __forceinline__ void gbar(unsigned e) {
    __syncthreads();
    if (threadIdx.x == 0) {
        __threadfence();
        unsigned a = atomicAdd(&g_cnt, 1u) + 1u;
        if (a == e * GRID) {
            g_rel = e;
        } else {
            while (g_rel < e) { __nanosleep(32); }
        }
        __threadfence();
    }
    __syncthreads();
}

// ---------------- init ----------------
__global__ void k_init(const float* __restrict__ h0, const float* __restrict__ c0) {
    int i = blockIdx.x * blockDim.x + threadIdx.x;
    if (i < BB * HH) { g_h[i] = h0[i]; g_c[i] = c0[i]; }
    if (i < BB * LL) g_mask[i] = 1.0f;
    if (i == 0) { g_cnt = 0u; g_rel = 0u; }
}

// ---------------- ctx precompute (proven correct in R2) ----------------
__global__ __launch_bounds__(256) void k_ctx(const float* __restrict__ Wc,
                                             const float* __restrict__ bc,
                                             const float* __restrict__ ctxin) {
    __shared__ float s_in[256][36];
    int b = blockIdx.x;
    int l0 = blockIdx.y * 32;
    int tid = threadIdx.x;
    int h0i = tid, h1i = tid + 256;

    float acc0[32], acc1[32];
    float bc0 = bc[h0i], bc1 = bc[h1i];
#pragma unroll
    for (int l = 0; l < 32; l++) { acc0[l] = bc0; acc1[l] = bc1; }

    for (int dc = 0; dc < HH; dc += 256) {
        __syncthreads();
        const float* src = ctxin + ((size_t)b * HH + dc + tid) * LL + l0;
#pragma unroll
        for (int l = 0; l < 32; l += 4) {
            float4 v = *reinterpret_cast<const float4*>(src + l);
            *reinterpret_cast<float4*>(&s_in[tid][l]) = v;
        }
        __syncthreads();

        const float* w0 = Wc + (size_t)h0i * HH + dc;
        const float* w1 = Wc + (size_t)h1i * HH + dc;
        for (int d4 = 0; d4 < 256; d4 += 4) {
            float4 wa = *reinterpret_cast<const float4*>(w0 + d4);
            float4 wb = *reinterpret_cast<const float4*>(w1 + d4);
            float wav[4] = {wa.x, wa.y, wa.z, wa.w};
            float wbv[4] = {wb.x, wb.y, wb.z, wb.w};
#pragma unroll
            for (int dd = 0; dd < 4; dd++) {
                float a = wav[dd], bw = wbv[dd];
#pragma unroll
                for (int l = 0; l < 32; l += 4) {
                    float4 s = *reinterpret_cast<const float4*>(&s_in[d4 + dd][l]);
                    acc0[l + 0] += a * s.x; acc0[l + 1] += a * s.y;
                    acc0[l + 2] += a * s.z; acc0[l + 3] += a * s.w;
                    acc1[l + 0] += bw * s.x; acc1[l + 1] += bw * s.y;
                    acc1[l + 2] += bw * s.z; acc1[l + 3] += bw * s.w;
                }
            }
        }
    }
#pragma unroll
    for (int l = 0; l < 32; l++) {
        size_t base = ((size_t)b * LL + l0 + l) * HH;
        g_ctx[base + h0i] = acc0[l];
        g_ctx[base + h1i] = acc1[l];
    }
}

// ---------------- persistent step kernel ----------------
__global__ __launch_bounds__(TPB, 1) void k_steps(
    const float* __restrict__ Whh, const float* __restrict__ bhh,
    const float* __restrict__ Win, const float* __restrict__ bin,
    const float* __restrict__ Wout, const float* __restrict__ bout,
    const float* __restrict__ V, float* __restrict__ out) {
    __shared__ float xs[16 * 512];     // 32KB staging: A 16x512, B 8x512, D 8x1024
    __shared__ float sm_inp[HH];
    __shared__ float sm_sc[LL];
    __shared__ float sm_alpha[LL];
    __shared__ float sm_mask[LL];
    __shared__ float sm_part[512];

    const int blk = blockIdx.x;
    const int tid = threadIdx.x, lane = tid & 31, w = tid >> 5;
    unsigned ep = 0;

    for (int t = 0; t < LL; t++) {
        // ======== Phase A: gates GEMM + LSTM cell ========
        // 128 blocks = 32 i-tiles (16 i) x 4 b-tiles (16 b); warp = 1 i x 4 gates x 16 b
        {
            int it = blk & 31, bt = blk >> 5;
            int ibase = it * 16, bbase = bt * 16;
            {
                const float4* src = (const float4*)(g_h + bbase * HH);
                float4* dst = (float4*)xs;
                for (int idx = tid; idx < 16 * 512 / 4; idx += TPB) dst[idx] = src[idx];
            }
            __syncthreads();

            int i = ibase + w;
            const float* wr0 = Whh + (size_t)(0 * HH + i) * HH;
            const float* wr1 = Whh + (size_t)(1 * HH + i) * HH;
            const float* wr2 = Whh + (size_t)(2 * HH + i) * HH;
            const float* wr3 = Whh + (size_t)(3 * HH + i) * HH;

            float acc[4][16];
#pragma unroll
            for (int g = 0; g < 4; g++)
#pragma unroll
                for (int b = 0; b < 16; b++) acc[g][b] = 0.f;

            float c0 = wr0[lane], c1 = wr1[lane], c2 = wr2[lane], c3 = wr3[lane];
            for (int kk = 0; kk < 16; kk++) {
                float n0 = 0.f, n1 = 0.f, n2 = 0.f, n3 = 0.f;
                if (kk < 15) {
                    int kn = (kk + 1) * 32 + lane;
                    n0 = wr0[kn]; n1 = wr1[kn]; n2 = wr2[kn]; n3 = wr3[kn];
                }
                int k = kk * 32 + lane;
#pragma unroll
                for (int b = 0; b < 16; b++) {
                    float hv = xs[b * 512 + k];
                    acc[0][b] += c0 * hv;
                    acc[1][b] += c1 * hv;
                    acc[2][b] += c2 * hv;
                    acc[3][b] += c3 * hv;
                }
                c0 = n0; c1 = n1; c2 = n2; c3 = n3;
            }

            float gate[4] = {0.f, 0.f, 0.f, 0.f};
#pragma unroll
            for (int g = 0; g < 4; g++)
#pragma unroll
                for (int b = 0; b < 16; b++) {
                    float vv = wsum(acc[g][b]);
                    if (lane == b) gate[g] = vv;
                }

            if (lane < 16) {
                int b = bbase + lane;
                float ig = gate[0] + bhh[0 * HH + i];
                float fg = gate[1] + bhh[1 * HH + i];
                float gg = gate[2] + bhh[2 * HH + i];
                float og = gate[3] + bhh[3 * HH + i];
                float c_old = g_c[b * HH + i];
                float si = 1.f / (1.f + expf(-ig));
                float sf = 1.f / (1.f + expf(-fg));
                float so = 1.f / (1.f + expf(-og));
                float ct = sf * c_old + si * tanhf(gg);
                float ht = so * tanhf(ct);
                g_c[b * HH + i] = ct;
                g_cat[b * 2 * HH + HH + i] = ht;
            }
        }
        gbar(++ep);

        // ======== Phase B: inp = W_in * h_t + b_in ========
        // 128 blocks = 16 r-tiles (32 r) x 8 b-tiles (8 b); warp = 2 r x 8 b
        {
            int rt = blk & 15, bt = blk >> 4;
            int bbase = bt * 8, r0 = rt * 32 + w * 2;
            for (int idx = tid; idx < 8 * 128; idx += TPB) {
                int b = idx >> 7, j = idx & 127;
                ((float4*)xs)[b * 128 + j] =
                    ((const float4*)(g_cat + (size_t)(bbase + b) * 2 * HH + HH))[j];
            }
            __syncthreads();

            const float* w0 = Win + (size_t)r0 * HH;
            const float* w1 = Win + (size_t)(r0 + 1) * HH;
            float acc[2][8];
#pragma unroll
            for (int r = 0; r < 2; r++)
#pragma unroll
                for (int b = 0; b < 8; b++) acc[r][b] = 0.f;

            float a0 = w0[lane], a1 = w1[lane];
            for (int kk = 0; kk < 16; kk++) {
                float na0 = 0.f, na1 = 0.f;
                if (kk < 15) {
                    int kn = (kk + 1) * 32 + lane;
                    na0 = w0[kn]; na1 = w1[kn];
                }
                int k = kk * 32 + lane;
#pragma unroll
                for (int b = 0; b < 8; b++) {
                    float xv = xs[b * 512 + k];
                    acc[0][b] += a0 * xv;
                    acc[1][b] += a1 * xv;
                }
                a0 = na0; a1 = na1;
            }

            float res[2] = {0.f, 0.f};
#pragma unroll
            for (int r = 0; r < 2; r++)
#pragma unroll
                for (int b = 0; b < 8; b++) {
                    float v = wsum(acc[r][b]);
                    if (lane == b) res[r] = v;
                }
            if (lane < 8) {
#pragma unroll
                for (int r = 0; r < 2; r++)
                    g_inp[(size_t)(bbase + lane) * HH + r0 + r] = res[r] + bin[r0 + r];
            }
        }
        gbar(++ep);

        // ======== Phase C1: scores (128 blocks: 2 per batch, 64 l each) ========
        {
            int b = blk >> 1, half = blk & 1;
            sm_inp[tid] = g_inp[b * HH + tid];
            __syncthreads();

            float inpv[16], Vv[16];
#pragma unroll
            for (int m = 0; m < 16; m++) {
                inpv[m] = sm_inp[m * 32 + lane];
                Vv[m] = V[m * 32 + lane];
            }
#pragma unroll
            for (int li = 0; li < 4; li++) {
                int l = half * 64 + w * 4 + li;
                const float* cp = g_ctx + ((size_t)b * LL + l) * HH + lane;
                float s = 0.f;
#pragma unroll
                for (int m = 0; m < 16; m++) {
                    float cv = cp[m * 32];
                    s += Vv[m] * fast_tanh(inpv[m] + cv);
                }
                s = wsum(s);
                if (lane == 0) g_sc[b * LL + l] = s;
            }
        }
        gbar(++ep);

        // ======== Phase C2: softmax + argmax + hid (128 blocks: 2 per batch, 256 h each) ========
        {
            int b = blk >> 1, half = blk & 1;
            if (tid < LL) {
                sm_sc[tid] = g_sc[b * LL + tid];
                sm_mask[tid] = g_mask[b * LL + tid];
            }
            __syncthreads();

            if (w == 0) {
                float sv[4], mk[4];
#pragma unroll
                for (int j = 0; j < 4; j++) {
                    mk[j] = sm_mask[lane + 32 * j];
                    sv[j] = (mk[j] != 0.f) ? sm_sc[lane + 32 * j] : -3.4e38f;
                }
                float m = fmaxf(fmaxf(sv[0], sv[1]), fmaxf(sv[2], sv[3]));
#pragma unroll
                for (int off = 16; off; off >>= 1)
                    m = fmaxf(m, __shfl_xor_sync(0xffffffffu, m, off));

                float e[4], sum = 0.f;
#pragma unroll
                for (int j = 0; j < 4; j++) {
                    e[j] = (mk[j] != 0.f) ? expf(sv[j] - m) : 0.f;
                    sum += e[j];
                }
                sum = wsum(sum);
                float inv = 1.f / sum;

                float best = -1.f;
                int bidx = 0;
#pragma unroll
                for (int j = 0; j < 4; j++) {
                    int l = lane + 32 * j;
                    float a = e[j] * inv;
                    sm_alpha[l] = a;
                    if (half == 0)
                        out[(size_t)b * LL * LL + (size_t)t * LL + l] = a;
                    float cand = (mk[j] != 0.f) ? a : -1.f;
                    if (cand > best) { best = cand; bidx = l; }
                }
#pragma unroll
                for (int off = 16; off; off >>= 1) {
                    float ob = __shfl_xor_sync(0xffffffffu, best, off);
                    int oi = __shfl_xor_sync(0xffffffffu, bidx, off);
                    if (ob > best || (ob == best && oi < bidx)) { best = ob; bidx = oi; }
                }
                if (half == 0 && lane == 0) {
                    out[OUT_PTR + b * LL + t] = (float)bidx;
                    g_bidx[b] = bidx;   // mask applied in phase D (avoids intra-phase race)
                }
            }
            __syncthreads();

            // hid over h in [half*256, half*256+256), l split across tid>>8
            {
                int lh = tid >> 8;               // 0/1 -> l range halves
                int hh = half * 256 + (tid & 255);
                const float* cp = g_ctx + (size_t)b * LL * HH + (size_t)(lh * 64) * HH + hh;
                float a = 0.f;
#pragma unroll 8
                for (int l = 0; l < 64; l++) a += cp[(size_t)l * HH] * sm_alpha[lh * 64 + l];
                sm_part[tid] = a;
            }
            __syncthreads();
            if (tid < 256)
                g_cat[b * 2 * HH + half * 256 + tid] = sm_part[tid] + sm_part[256 + tid];
        }
        gbar(++ep);

        // ======== Phase D: h = tanh(W_out * [hid, h_t] + b_out) + mask update ========
        // 128 blocks = 16 r-tiles (32 r) x 8 b-tiles (8 b); warp = 2 r x 8 b
        {
            if (blk == 0 && tid < BB)
                g_mask[tid * LL + g_bidx[tid]] = 0.f;

            int rt = blk & 15, bt = blk >> 4;
            int bbase = bt * 8, r0 = rt * 32 + w * 2;
            {
                const float4* src = (const float4*)(g_cat + (size_t)bbase * 2 * HH);
                float4* dst = (float4*)xs;
                for (int idx = tid; idx < 8 * 1024 / 4; idx += TPB) dst[idx] = src[idx];
            }
            __syncthreads();

            const float* w0 = Wout + (size_t)r0 * 2 * HH;
            const float* w1 = Wout + (size_t)(r0 + 1) * 2 * HH;
            float acc[2][8];
#pragma unroll
            for (int r = 0; r < 2; r++)
#pragma unroll
                for (int b = 0; b < 8; b++) acc[r][b] = 0.f;

            float a0 = w0[lane], a1 = w1[lane];
            for (int kk = 0; kk < 32; kk++) {
                float na0 = 0.f, na1 = 0.f;
                if (kk < 31) {
                    int kn = (kk + 1) * 32 + lane;
                    na0 = w0[kn]; na1 = w1[kn];
                }
                int k = kk * 32 + lane;
#pragma unroll
                for (int b = 0; b < 8; b++) {
                    float xv = xs[b * 1024 + k];
                    acc[0][b] += a0 * xv;
                    acc[1][b] += a1 * xv;
                }
                a0 = na0; a1 = na1;
            }

            float res[2] = {0.f, 0.f};
#pragma unroll
            for (int r = 0; r < 2; r++)
#pragma unroll
                for (int b = 0; b < 8; b++) {
                    float v = wsum(acc[r][b]);
                    if (lane == b) res[r] = v;
                }
            if (lane < 8) {
#pragma unroll
                for (int r = 0; r < 2; r++)
                    g_h[(size_t)(bbase + lane) * HH + r0 + r] =
                        tanhf(res[r] + bout[r0 + r]);
            }
        }
        gbar(++ep);
    }

    // final h/c copy
    for (int i = blk * TPB + tid; i < BB * HH; i += GRID * TPB) {
        out[OUT_H + i] = g_h[i];
        out[OUT_C + i] = g_c[i];
    }
}

extern "C" void kernel_launch(void* const* d_in, const int* in_sizes, int n_in,
                              void* d_out, int out_size) {
    const float* h0   = (const float*)d_in[2];
    const float* c0   = (const float*)d_in[3];
    const float* ctxi = (const float*)d_in[4];
    const float* Whh  = (const float*)d_in[5];
    const float* bhh  = (const float*)d_in[6];
    const float* Win  = (const float*)d_in[7];
    const float* bin  = (const float*)d_in[8];
    const float* Wc   = (const float*)d_in[9];
    const float* bc   = (const float*)d_in[10];
    const float* V    = (const float*)d_in[11];
    const float* Wout = (const float*)d_in[12];
    const float* bout = (const float*)d_in[13];
    float* out = (float*)d_out;

    k_init<<<GRID, 256>>>(h0, c0);
    k_ctx<<<dim3(BB, LL / 32), 256>>>(Wc, bc, ctxi);
    k_steps<<<GRID, TPB>>>(Whh, bhh, Win, bin, Wout, bout, V, out);
}

// round 6
// speedup vs baseline: 1.5474x; 1.0786x over previous
#include <cuda_runtime.h>

#define BB 64
#define HH 512
#define LL 128
#define GRID 128
#define TPB 512

// persistent state
__device__ float g_ctx[(size_t)BB * LL * HH];  // [b][l][h]
__device__ float g_h[BB * HH];
__device__ float g_c[BB * HH];
__device__ float g_cat[BB * 2 * HH];           // [b][0:512]=hid, [512:1024]=h_t
__device__ float g_inp[BB * HH];
__device__ float g_mask[BB * LL];
__device__ float g_sc[BB * LL];
__device__ int   g_bidx[BB];

// flag barrier state (contention-free)
__device__ volatile unsigned g_arrive[GRID];
__device__ volatile unsigned g_rel;

#define OUT_PTR  (BB * LL * LL)
#define OUT_H    (OUT_PTR + BB * LL)
#define OUT_C    (OUT_H + BB * HH)

__device__ __forceinline__ float wsum(float v) {
#pragma unroll
    for (int off = 16; off; off >>= 1) v += __shfl_xor_sync(0xffffffffu, v, off);
    return v;
}

__device__ __forceinline__ float fast_tanh(float x) {
    float e = __expf(2.0f * x);
    return 1.0f - __fdividef(2.0f, e + 1.0f);
}

// packed f32x2 FMA: d += a * b (elementwise)
__device__ __forceinline__ void ffma2(float2& d, float2 a, float2 b) {
    asm("{\n\t"
        ".reg .b64 ra, rb, rd;\n\t"
        "mov.b64 ra, {%2, %3};\n\t"
        "mov.b64 rb, {%4, %5};\n\t"
        "mov.b64 rd, {%0, %1};\n\t"
        "fma.rn.f32x2 rd, ra, rb, rd;\n\t"
        "mov.b64 {%0, %1}, rd;\n\t"
        "}"
        : "+f"(d.x), "+f"(d.y)
        : "f"(a.x), "f"(a.y), "f"(b.x), "f"(b.y));
}

// flag-based grid barrier: parallel arrivals, single release word, bounded backoff
__device__ __forceinline__ void gbar(unsigned e) {
    __syncthreads();
    if (threadIdx.x == 0) {
        __threadfence();               // publish this block's phase writes
        g_arrive[blockIdx.x] = e;
    }
    if (blockIdx.x == 0) {
        if (threadIdx.x < GRID) {
            while (g_arrive[threadIdx.x] < e) { __nanosleep(20); }
        }
        __syncthreads();
        if (threadIdx.x == 0) g_rel = e;
    }
    if (threadIdx.x == 0) {
        while (g_rel < e) { __nanosleep(20); }
        __threadfence();               // acquire (CCTL.IVALL: fresh L1)
    }
    __syncthreads();
}

// ---------------- init ----------------
__global__ void k_init(const float* __restrict__ h0, const float* __restrict__ c0) {
    int i = blockIdx.x * blockDim.x + threadIdx.x;
    if (i < BB * HH) { g_h[i] = h0[i]; g_c[i] = c0[i]; }
    if (i < BB * LL) g_mask[i] = 1.0f;
    if (i < GRID) g_arrive[i] = 0u;
    if (i == 0) g_rel = 0u;
}

// ---------------- ctx precompute (proven correct) ----------------
__global__ __launch_bounds__(256) void k_ctx(const float* __restrict__ Wc,
                                             const float* __restrict__ bc,
                                             const float* __restrict__ ctxin) {
    __shared__ float s_in[256][36];
    int b = blockIdx.x;
    int l0 = blockIdx.y * 32;
    int tid = threadIdx.x;
    int h0i = tid, h1i = tid + 256;

    float acc0[32], acc1[32];
    float bc0 = bc[h0i], bc1 = bc[h1i];
#pragma unroll
    for (int l = 0; l < 32; l++) { acc0[l] = bc0; acc1[l] = bc1; }

    for (int dc = 0; dc < HH; dc += 256) {
        __syncthreads();
        const float* src = ctxin + ((size_t)b * HH + dc + tid) * LL + l0;
#pragma unroll
        for (int l = 0; l < 32; l += 4) {
            float4 v = *reinterpret_cast<const float4*>(src + l);
            *reinterpret_cast<float4*>(&s_in[tid][l]) = v;
        }
        __syncthreads();

        const float* w0 = Wc + (size_t)h0i * HH + dc;
        const float* w1 = Wc + (size_t)h1i * HH + dc;
        for (int d4 = 0; d4 < 256; d4 += 4) {
            float4 wa = *reinterpret_cast<const float4*>(w0 + d4);
            float4 wb = *reinterpret_cast<const float4*>(w1 + d4);
            float wav[4] = {wa.x, wa.y, wa.z, wa.w};
            float wbv[4] = {wb.x, wb.y, wb.z, wb.w};
#pragma unroll
            for (int dd = 0; dd < 4; dd++) {
                float a = wav[dd], bw = wbv[dd];
#pragma unroll
                for (int l = 0; l < 32; l += 4) {
                    float4 s = *reinterpret_cast<const float4*>(&s_in[d4 + dd][l]);
                    acc0[l + 0] += a * s.x; acc0[l + 1] += a * s.y;
                    acc0[l + 2] += a * s.z; acc0[l + 3] += a * s.w;
                    acc1[l + 0] += bw * s.x; acc1[l + 1] += bw * s.y;
                    acc1[l + 2] += bw * s.z; acc1[l + 3] += bw * s.w;
                }
            }
        }
    }
#pragma unroll
    for (int l = 0; l < 32; l++) {
        size_t base = ((size_t)b * LL + l0 + l) * HH;
        g_ctx[base + h0i] = acc0[l];
        g_ctx[base + h1i] = acc1[l];
    }
}

// ---------------- persistent step kernel ----------------
__global__ __launch_bounds__(TPB, 1) void k_steps(
    const float* __restrict__ Whh, const float* __restrict__ bhh,
    const float* __restrict__ Win, const float* __restrict__ bin,
    const float* __restrict__ Wout, const float* __restrict__ bout,
    const float* __restrict__ V, float* __restrict__ out) {
    __shared__ float xs[16 * 512];     // 32KB staging
    __shared__ float sm_inp[HH];
    __shared__ float sm_sc[LL];
    __shared__ float sm_alpha[LL];
    __shared__ float sm_mask[LL];
    __shared__ float sm_part[512];

    const int blk = blockIdx.x;
    const int tid = threadIdx.x, lane = tid & 31, w = tid >> 5;
    unsigned ep = 0;

    for (int t = 0; t < LL; t++) {
        // ======== Phase A: gates GEMM (f32x2) + LSTM cell ========
        // 256 vtiles = 64 i-tiles (8 i) x 4 b-tiles (16 b); 2 per block.
        // Warp: 1 i x 4 gates x 8 b (k paired).
#pragma unroll 1
        for (int sub = 0; sub < 2; sub++) {
            int vt = blk + sub * GRID;
            int it = vt & 63, bt = vt >> 6;
            int ibase = it * 8, bbase = bt * 16;
            __syncthreads();
            {
                const float4* src = (const float4*)(g_h + bbase * HH);
                float4* dst = (float4*)xs;
                for (int idx = tid; idx < 16 * 512 / 4; idx += TPB)
                    dst[idx] = __ldcg(src + idx);
            }
            __syncthreads();

            int i = ibase + (w >> 1);
            int bh = (w & 1) * 8;
            const float* wr0 = Whh + (size_t)(0 * HH + i) * HH;
            const float* wr1 = Whh + (size_t)(1 * HH + i) * HH;
            const float* wr2 = Whh + (size_t)(2 * HH + i) * HH;
            const float* wr3 = Whh + (size_t)(3 * HH + i) * HH;

            float2 acc[4][8];
#pragma unroll
            for (int g = 0; g < 4; g++)
#pragma unroll
                for (int b = 0; b < 8; b++) acc[g][b] = make_float2(0.f, 0.f);

            float2 c0 = *(const float2*)(wr0 + lane * 2);
            float2 c1 = *(const float2*)(wr1 + lane * 2);
            float2 c2 = *(const float2*)(wr2 + lane * 2);
            float2 c3 = *(const float2*)(wr3 + lane * 2);
#pragma unroll
            for (int kk = 0; kk < 8; kk++) {
                float2 n0, n1, n2, n3;
                if (kk < 7) {
                    int kn = (kk + 1) * 64 + lane * 2;
                    n0 = *(const float2*)(wr0 + kn);
                    n1 = *(const float2*)(wr1 + kn);
                    n2 = *(const float2*)(wr2 + kn);
                    n3 = *(const float2*)(wr3 + kn);
                }
                int k = kk * 64 + lane * 2;
#pragma unroll
                for (int b = 0; b < 8; b++) {
                    float2 hv = *(const float2*)&xs[(bh + b) * 512 + k];
                    ffma2(acc[0][b], c0, hv);
                    ffma2(acc[1][b], c1, hv);
                    ffma2(acc[2][b], c2, hv);
                    ffma2(acc[3][b], c3, hv);
                }
                if (kk < 7) { c0 = n0; c1 = n1; c2 = n2; c3 = n3; }
            }

            float gate[4] = {0.f, 0.f, 0.f, 0.f};
#pragma unroll
            for (int g = 0; g < 4; g++)
#pragma unroll
                for (int b = 0; b < 8; b++) {
                    float vv = wsum(acc[g][b].x + acc[g][b].y);
                    if (lane == b) gate[g] = vv;
                }

            if (lane < 8) {
                int b = bbase + bh + lane;
                float ig = gate[0] + bhh[0 * HH + i];
                float fg = gate[1] + bhh[1 * HH + i];
                float gg = gate[2] + bhh[2 * HH + i];
                float og = gate[3] + bhh[3 * HH + i];
                float c_old = g_c[b * HH + i];
                float si = 1.f / (1.f + expf(-ig));
                float sf = 1.f / (1.f + expf(-fg));
                float so = 1.f / (1.f + expf(-og));
                float ct = sf * c_old + si * tanhf(gg);
                float ht = so * tanhf(ct);
                g_c[b * HH + i] = ct;
                g_cat[b * 2 * HH + HH + i] = ht;
            }
        }
        gbar(++ep);

        // ======== Phase B: inp = W_in * h_t + b_in (f32x2) ========
        // 128 blocks = 16 r-tiles (32 r) x 8 b-tiles (8 b); warp = 2 r x 8 b.
        {
            int rt = blk & 15, bt = blk >> 4;
            int bbase = bt * 8, r0 = rt * 32 + w * 2;
            for (int idx = tid; idx < 8 * 128; idx += TPB) {
                int b = idx >> 7, j = idx & 127;
                ((float4*)xs)[b * 128 + j] =
                    __ldcg((const float4*)(g_cat + (size_t)(bbase + b) * 2 * HH + HH) + j);
            }
            __syncthreads();

            const float* w0 = Win + (size_t)r0 * HH;
            const float* w1 = Win + (size_t)(r0 + 1) * HH;
            float2 acc[2][8];
#pragma unroll
            for (int r = 0; r < 2; r++)
#pragma unroll
                for (int b = 0; b < 8; b++) acc[r][b] = make_float2(0.f, 0.f);

            float2 a0 = *(const float2*)(w0 + lane * 2);
            float2 a1 = *(const float2*)(w1 + lane * 2);
#pragma unroll
            for (int kk = 0; kk < 8; kk++) {
                float2 na0, na1;
                if (kk < 7) {
                    int kn = (kk + 1) * 64 + lane * 2;
                    na0 = *(const float2*)(w0 + kn);
                    na1 = *(const float2*)(w1 + kn);
                }
                int k = kk * 64 + lane * 2;
#pragma unroll
                for (int b = 0; b < 8; b++) {
                    float2 xv = *(const float2*)&xs[b * 512 + k];
                    ffma2(acc[0][b], a0, xv);
                    ffma2(acc[1][b], a1, xv);
                }
                if (kk < 7) { a0 = na0; a1 = na1; }
            }

            float res[2] = {0.f, 0.f};
#pragma unroll
            for (int r = 0; r < 2; r++)
#pragma unroll
                for (int b = 0; b < 8; b++) {
                    float v = wsum(acc[r][b].x + acc[r][b].y);
                    if (lane == b) res[r] = v;
                }
            if (lane < 8) {
#pragma unroll
                for (int r = 0; r < 2; r++)
                    g_inp[(size_t)(bbase + lane) * HH + r0 + r] = res[r] + bin[r0 + r];
            }
        }
        gbar(++ep);

        // ======== Phase C1: scores (2 blocks per batch, 64 l each) ========
        {
            int b = blk >> 1, half = blk & 1;
            sm_inp[tid] = __ldcg(&g_inp[b * HH + tid]);
            __syncthreads();

            float inpv[16], Vv[16];
#pragma unroll
            for (int m = 0; m < 16; m++) {
                inpv[m] = sm_inp[m * 32 + lane];
                Vv[m] = V[m * 32 + lane];
            }
#pragma unroll
            for (int li = 0; li < 4; li++) {
                int l = half * 64 + w * 4 + li;
                const float* cp = g_ctx + ((size_t)b * LL + l) * HH + lane;
                float s = 0.f;
#pragma unroll
                for (int m = 0; m < 16; m++) {
                    float cv = __ldcg(cp + m * 32);
                    s += Vv[m] * fast_tanh(inpv[m] + cv);
                }
                s = wsum(s);
                if (lane == 0) g_sc[b * LL + l] = s;
            }
        }
        gbar(++ep);

        // ======== Phase C2: softmax + argmax + hid (2 blocks per batch) ========
        {
            int b = blk >> 1, half = blk & 1;
            if (tid < LL) {
                sm_sc[tid] = __ldcg(&g_sc[b * LL + tid]);
                sm_mask[tid] = g_mask[b * LL + tid];
            }
            __syncthreads();

            if (w == 0) {
                float sv[4], mk[4];
#pragma unroll
                for (int j = 0; j < 4; j++) {
                    mk[j] = sm_mask[lane + 32 * j];
                    sv[j] = (mk[j] != 0.f) ? sm_sc[lane + 32 * j] : -3.4e38f;
                }
                float m = fmaxf(fmaxf(sv[0], sv[1]), fmaxf(sv[2], sv[3]));
#pragma unroll
                for (int off = 16; off; off >>= 1)
                    m = fmaxf(m, __shfl_xor_sync(0xffffffffu, m, off));

                float e[4], sum = 0.f;
#pragma unroll
                for (int j = 0; j < 4; j++) {
                    e[j] = (mk[j] != 0.f) ? expf(sv[j] - m) : 0.f;
                    sum += e[j];
                }
                sum = wsum(sum);
                float inv = 1.f / sum;

                float best = -1.f;
                int bidx = 0;
#pragma unroll
                for (int j = 0; j < 4; j++) {
                    int l = lane + 32 * j;
                    float a = e[j] * inv;
                    sm_alpha[l] = a;
                    if (half == 0)
                        out[(size_t)b * LL * LL + (size_t)t * LL + l] = a;
                    float cand = (mk[j] != 0.f) ? a : -1.f;
                    if (cand > best) { best = cand; bidx = l; }
                }
#pragma unroll
                for (int off = 16; off; off >>= 1) {
                    float ob = __shfl_xor_sync(0xffffffffu, best, off);
                    int oi = __shfl_xor_sync(0xffffffffu, bidx, off);
                    if (ob > best || (ob == best && oi < bidx)) { best = ob; bidx = oi; }
                }
                if (half == 0 && lane == 0) {
                    out[OUT_PTR + b * LL + t] = (float)bidx;
                    g_bidx[b] = bidx;
                }
            }
            __syncthreads();

            {
                int lh = tid >> 8;
                int hh = half * 256 + (tid & 255);
                const float* cp = g_ctx + (size_t)b * LL * HH + (size_t)(lh * 64) * HH + hh;
                float a = 0.f;
#pragma unroll 8
                for (int l = 0; l < 64; l++) a += __ldcg(cp + (size_t)l * HH) * sm_alpha[lh * 64 + l];
                sm_part[tid] = a;
            }
            __syncthreads();
            if (tid < 256)
                g_cat[b * 2 * HH + half * 256 + tid] = sm_part[tid] + sm_part[256 + tid];
        }
        gbar(++ep);

        // ======== Phase D: h = tanh(W_out * [hid, h_t] + b_out) + mask update ========
        {
            if (blk == 0 && tid < BB)
                g_mask[tid * LL + g_bidx[tid]] = 0.f;

            int rt = blk & 15, bt = blk >> 4;
            int bbase = bt * 8, r0 = rt * 32 + w * 2;
            {
                const float4* src = (const float4*)(g_cat + (size_t)bbase * 2 * HH);
                float4* dst = (float4*)xs;
                for (int idx = tid; idx < 8 * 1024 / 4; idx += TPB)
                    dst[idx] = __ldcg(src + idx);
            }
            __syncthreads();

            const float* w0 = Wout + (size_t)r0 * 2 * HH;
            const float* w1 = Wout + (size_t)(r0 + 1) * 2 * HH;
            float2 acc[2][8];
#pragma unroll
            for (int r = 0; r < 2; r++)
#pragma unroll
                for (int b = 0; b < 8; b++) acc[r][b] = make_float2(0.f, 0.f);

            float2 a0 = *(const float2*)(w0 + lane * 2);
            float2 a1 = *(const float2*)(w1 + lane * 2);
#pragma unroll
            for (int kk = 0; kk < 16; kk++) {
                float2 na0, na1;
                if (kk < 15) {
                    int kn = (kk + 1) * 64 + lane * 2;
                    na0 = *(const float2*)(w0 + kn);
                    na1 = *(const float2*)(w1 + kn);
                }
                int k = kk * 64 + lane * 2;
#pragma unroll
                for (int b = 0; b < 8; b++) {
                    float2 xv = *(const float2*)&xs[b * 1024 + k];
                    ffma2(acc[0][b], a0, xv);
                    ffma2(acc[1][b], a1, xv);
                }
                if (kk < 15) { a0 = na0; a1 = na1; }
            }

            float res[2] = {0.f, 0.f};
#pragma unroll
            for (int r = 0; r < 2; r++)
#pragma unroll
                for (int b = 0; b < 8; b++) {
                    float v = wsum(acc[r][b].x + acc[r][b].y);
                    if (lane == b) res[r] = v;
                }
            if (lane < 8) {
#pragma unroll
                for (int r = 0; r < 2; r++)
                    g_h[(size_t)(bbase + lane) * HH + r0 + r] =
                        tanhf(res[r] + bout[r0 + r]);
            }
        }
        gbar(++ep);
    }

    // final h/c copy
    for (int i = blk * TPB + tid; i < BB * HH; i += GRID * TPB) {
        out[OUT_H + i] = g_h[i];
        out[OUT_C + i] = g_c[i];
    }
}

extern "C" void kernel_launch(void* const* d_in, const int* in_sizes, int n_in,
                              void* d_out, int out_size) {
    const float* h0   = (const float*)d_in[2];
    const float* c0   = (const float*)d_in[3];
    const float* ctxi = (const float*)d_in[4];
    const float* Whh  = (const float*)d_in[5];
    const float* bhh  = (const float*)d_in[6];
    const float* Win  = (const float*)d_in[7];
    const float* bin  = (const float*)d_in[8];
    const float* Wc   = (const float*)d_in[9];
    const float* bc   = (const float*)d_in[10];
    const float* V    = (const float*)d_in[11];
    const float* Wout = (const float*)d_in[12];
    const float* bout = (const float*)d_in[13];
    float* out = (float*)d_out;

    k_init<<<GRID, 256>>>(h0, c0);
    k_ctx<<<dim3(BB, LL / 32), 256>>>(Wc, bc, ctxi);
    k_steps<<<GRID, TPB>>>(Whh, bhh, Win, bin, Wout, bout, V, out);
}

// round 7
// speedup vs baseline: 1.6400x; 1.0598x over previous
#include <cuda_runtime.h>

#define BB 64
#define HH 512
#define LL 128
#define GRID 128
#define TPB 512

// persistent state
__device__ float g_ctx[(size_t)BB * LL * HH];  // [b][l][h]
__device__ float g_h[BB * HH];
__device__ float g_c[BB * HH];
__device__ float g_cat[BB * 2 * HH];           // [b][0:512]=hid, [512:1024]=h_t
__device__ float g_inp[BB * HH];
__device__ float g_mask[BB * LL];
__device__ float g_sc[BB * LL];
__device__ int   g_bidx[BB];

// flag barrier state; epochs persist across calls (base read at kernel entry)
__device__ volatile unsigned g_arrive[GRID];
__device__ volatile unsigned g_rel;

#define OUT_PTR  (BB * LL * LL)
#define OUT_H    (OUT_PTR + BB * LL)
#define OUT_C    (OUT_H + BB * HH)

__device__ __forceinline__ float wsum(float v) {
#pragma unroll
    for (int off = 16; off; off >>= 1) v += __shfl_xor_sync(0xffffffffu, v, off);
    return v;
}

__device__ __forceinline__ float fast_tanh(float x) {
    float e = __expf(2.0f * x);
    return 1.0f - __fdividef(2.0f, e + 1.0f);
}

// packed f32x2 FMA: d += a * b (elementwise)
__device__ __forceinline__ void ffma2(float2& d, float2 a, float2 b) {
    asm("{\n\t"
        ".reg .b64 ra, rb, rd;\n\t"
        "mov.b64 ra, {%2, %3};\n\t"
        "mov.b64 rb, {%4, %5};\n\t"
        "mov.b64 rd, {%0, %1};\n\t"
        "fma.rn.f32x2 rd, ra, rb, rd;\n\t"
        "mov.b64 {%0, %1}, rd;\n\t"
        "}"
        : "+f"(d.x), "+f"(d.y)
        : "f"(a.x), "f"(a.y), "f"(b.x), "f"(b.y));
}

// flag-based grid barrier with absolute epoch e
__device__ __forceinline__ void gbar(unsigned e) {
    __syncthreads();
    if (threadIdx.x == 0) {
        __threadfence();               // publish this block's phase writes
        g_arrive[blockIdx.x] = e;
    }
    if (blockIdx.x == 0) {
        if (threadIdx.x < GRID) {
            while (g_arrive[threadIdx.x] < e) { __nanosleep(20); }
        }
        __syncthreads();
        if (threadIdx.x == 0) g_rel = e;
    }
    if (threadIdx.x == 0) {
        while (g_rel < e) { __nanosleep(20); }
        __threadfence();               // acquire (IVALL: fresh L1)
    }
    __syncthreads();
}

// cluster pair sync (blocks 2b, 2b+1)
__device__ __forceinline__ void csync() {
    __syncthreads();
    __threadfence();   // make this thread's global writes visible pair-wide (L2)
    asm volatile("barrier.cluster.arrive.aligned;" ::: "memory");
    asm volatile("barrier.cluster.wait.aligned;" ::: "memory");
    __syncthreads();
}

// ---------------- single persistent kernel: init + ctx + 128 steps ----------------
__global__ __launch_bounds__(TPB, 1) __cluster_dims__(2, 1, 1) void k_all(
    const float* __restrict__ h0, const float* __restrict__ c0,
    const float* __restrict__ ctxin,
    const float* __restrict__ Wc, const float* __restrict__ bc,
    const float* __restrict__ Whh, const float* __restrict__ bhh,
    const float* __restrict__ Win, const float* __restrict__ bin,
    const float* __restrict__ Wout, const float* __restrict__ bout,
    const float* __restrict__ V, float* __restrict__ out) {
    __shared__ float xs[16 * 512];     // 32KB staging (GEMM tiles / ctx staging)
    __shared__ float sm_inp[HH];
    __shared__ float sm_sc[LL];
    __shared__ float sm_alpha[LL];
    __shared__ float sm_mask[LL];
    __shared__ float sm_part[512];

    const int blk = blockIdx.x;
    const int tid = threadIdx.x, lane = tid & 31, w = tid >> 5;

    // base epoch from previous call (0 when cold); stable until first gbar release
    unsigned ep = g_rel;

    // ======== init phase ========
    {
        int gi = blk * TPB + tid;
        if (gi < BB * HH) { g_h[gi] = h0[gi]; g_c[gi] = c0[gi]; }
        if (gi < BB * LL) g_mask[gi] = 1.0f;
    }
    gbar(++ep);

    // ======== ctx precompute: ctx[b,l,h] = sum_d Wc[h,d]*ctxin[b,d,l] + bc[h] ========
    // 256 tiles (b, l0); 2 per block; thread = 1 h, 32 l (16 float2 acc)
#pragma unroll 1
    for (int sub = 0; sub < 2; sub++) {
        int v = blk + sub * GRID;
        int b = v >> 2, l0 = (v & 3) * 32;

        float2 acc[16];
#pragma unroll
        for (int p = 0; p < 16; p++) acc[p] = make_float2(0.f, 0.f);

        for (int dc = 0; dc < HH; dc += 128) {
            __syncthreads();
            // stage ctxin[b, dc..dc+128, l0..l0+32] -> xs as [128][36]
            for (int fi = tid; fi < 1024; fi += TPB) {
                int di = fi >> 3, lq = fi & 7;
                float4 val = __ldcg((const float4*)(ctxin +
                    ((size_t)b * HH + dc + di) * LL + l0 + lq * 4));
                *(float4*)&xs[di * 36 + lq * 4] = val;
            }
            __syncthreads();

            const float* wrow = Wc + (size_t)tid * HH + dc;
            for (int d4 = 0; d4 < 128; d4 += 4) {
                float4 wq = *(const float4*)(wrow + d4);
                float wv[4] = {wq.x, wq.y, wq.z, wq.w};
#pragma unroll
                for (int j = 0; j < 4; j++) {
                    float2 ws = make_float2(wv[j], wv[j]);
                    const float2* srow = (const float2*)&xs[(d4 + j) * 36];
#pragma unroll
                    for (int p = 0; p < 16; p++) ffma2(acc[p], ws, srow[p]);
                }
            }
        }
        float bcv = bc[tid];
#pragma unroll
        for (int p = 0; p < 16; p++) {
            size_t base = ((size_t)b * LL + l0 + 2 * p) * HH + tid;
            g_ctx[base] = acc[p].x + bcv;
            g_ctx[base + HH] = acc[p].y + bcv;
        }
    }
    gbar(++ep);

    // ======== step loop ========
    for (int t = 0; t < LL; t++) {
        // ---- Phase A: gates GEMM (f32x2) + LSTM cell ----
        // 256 vtiles = 64 i-tiles (8 i) x 4 b-tiles (16 b); 2 per block.
#pragma unroll 1
        for (int sub = 0; sub < 2; sub++) {
            int vt = blk + sub * GRID;
            int it = vt & 63, bt = vt >> 6;
            int ibase = it * 8, bbase = bt * 16;
            __syncthreads();
            {
                const float4* src = (const float4*)(g_h + bbase * HH);
                float4* dst = (float4*)xs;
                for (int idx = tid; idx < 16 * 512 / 4; idx += TPB)
                    dst[idx] = __ldcg(src + idx);
            }
            __syncthreads();

            int i = ibase + (w >> 1);
            int bh = (w & 1) * 8;
            const float* wr0 = Whh + (size_t)(0 * HH + i) * HH;
            const float* wr1 = Whh + (size_t)(1 * HH + i) * HH;
            const float* wr2 = Whh + (size_t)(2 * HH + i) * HH;
            const float* wr3 = Whh + (size_t)(3 * HH + i) * HH;

            float2 acc[4][8];
#pragma unroll
            for (int g = 0; g < 4; g++)
#pragma unroll
                for (int b = 0; b < 8; b++) acc[g][b] = make_float2(0.f, 0.f);

            float2 c0v = *(const float2*)(wr0 + lane * 2);
            float2 c1v = *(const float2*)(wr1 + lane * 2);
            float2 c2v = *(const float2*)(wr2 + lane * 2);
            float2 c3v = *(const float2*)(wr3 + lane * 2);
#pragma unroll
            for (int kk = 0; kk < 8; kk++) {
                float2 n0, n1, n2, n3;
                if (kk < 7) {
                    int kn = (kk + 1) * 64 + lane * 2;
                    n0 = *(const float2*)(wr0 + kn);
                    n1 = *(const float2*)(wr1 + kn);
                    n2 = *(const float2*)(wr2 + kn);
                    n3 = *(const float2*)(wr3 + kn);
                }
                int k = kk * 64 + lane * 2;
#pragma unroll
                for (int b = 0; b < 8; b++) {
                    float2 hv = *(const float2*)&xs[(bh + b) * 512 + k];
                    ffma2(acc[0][b], c0v, hv);
                    ffma2(acc[1][b], c1v, hv);
                    ffma2(acc[2][b], c2v, hv);
                    ffma2(acc[3][b], c3v, hv);
                }
                if (kk < 7) { c0v = n0; c1v = n1; c2v = n2; c3v = n3; }
            }

            float gate[4] = {0.f, 0.f, 0.f, 0.f};
#pragma unroll
            for (int g = 0; g < 4; g++)
#pragma unroll
                for (int b = 0; b < 8; b++) {
                    float vv = wsum(acc[g][b].x + acc[g][b].y);
                    if (lane == b) gate[g] = vv;
                }

            if (lane < 8) {
                int b = bbase + bh + lane;
                float ig = gate[0] + bhh[0 * HH + i];
                float fg = gate[1] + bhh[1 * HH + i];
                float gg = gate[2] + bhh[2 * HH + i];
                float og = gate[3] + bhh[3 * HH + i];
                float c_old = g_c[b * HH + i];
                float si = 1.f / (1.f + expf(-ig));
                float sf = 1.f / (1.f + expf(-fg));
                float so = 1.f / (1.f + expf(-og));
                float ct = sf * c_old + si * tanhf(gg);
                float ht = so * tanhf(ct);
                g_c[b * HH + i] = ct;
                g_cat[b * 2 * HH + HH + i] = ht;
            }
        }
        gbar(++ep);

        // ---- Phase B: inp = W_in * h_t + b_in (f32x2) ----
        {
            int rt = blk & 15, bt = blk >> 4;
            int bbase = bt * 8, r0 = rt * 32 + w * 2;
            for (int idx = tid; idx < 8 * 128; idx += TPB) {
                int b = idx >> 7, j = idx & 127;
                ((float4*)xs)[b * 128 + j] =
                    __ldcg((const float4*)(g_cat + (size_t)(bbase + b) * 2 * HH + HH) + j);
            }
            __syncthreads();

            const float* w0 = Win + (size_t)r0 * HH;
            const float* w1 = Win + (size_t)(r0 + 1) * HH;
            float2 acc[2][8];
#pragma unroll
            for (int r = 0; r < 2; r++)
#pragma unroll
                for (int b = 0; b < 8; b++) acc[r][b] = make_float2(0.f, 0.f);

            float2 a0 = *(const float2*)(w0 + lane * 2);
            float2 a1 = *(const float2*)(w1 + lane * 2);
#pragma unroll
            for (int kk = 0; kk < 8; kk++) {
                float2 na0, na1;
                if (kk < 7) {
                    int kn = (kk + 1) * 64 + lane * 2;
                    na0 = *(const float2*)(w0 + kn);
                    na1 = *(const float2*)(w1 + kn);
                }
                int k = kk * 64 + lane * 2;
#pragma unroll
                for (int b = 0; b < 8; b++) {
                    float2 xv = *(const float2*)&xs[b * 512 + k];
                    ffma2(acc[0][b], a0, xv);
                    ffma2(acc[1][b], a1, xv);
                }
                if (kk < 7) { a0 = na0; a1 = na1; }
            }

            float res[2] = {0.f, 0.f};
#pragma unroll
            for (int r = 0; r < 2; r++)
#pragma unroll
                for (int b = 0; b < 8; b++) {
                    float vv = wsum(acc[r][b].x + acc[r][b].y);
                    if (lane == b) res[r] = vv;
                }
            if (lane < 8) {
#pragma unroll
                for (int r = 0; r < 2; r++)
                    g_inp[(size_t)(bbase + lane) * HH + r0 + r] = res[r] + bin[r0 + r];
            }
        }
        gbar(++ep);

        // ---- Phase C1: scores (cluster pair: 2 blocks per batch, 64 l each) ----
        {
            int b = blk >> 1, half = blk & 1;
            sm_inp[tid] = __ldcg(&g_inp[b * HH + tid]);
            __syncthreads();

            float inpv[16], Vv[16];
#pragma unroll
            for (int m = 0; m < 16; m++) {
                inpv[m] = sm_inp[m * 32 + lane];
                Vv[m] = V[m * 32 + lane];
            }
#pragma unroll
            for (int li = 0; li < 4; li++) {
                int l = half * 64 + w * 4 + li;
                const float* cp = g_ctx + ((size_t)b * LL + l) * HH + lane;
                float s = 0.f;
#pragma unroll
                for (int m = 0; m < 16; m++) {
                    float cv = __ldcg(cp + m * 32);
                    s += Vv[m] * fast_tanh(inpv[m] + cv);
                }
                s = wsum(s);
                if (lane == 0) g_sc[b * LL + l] = s;
            }
        }
        csync();   // pair-local: scores of both halves now visible

        // ---- Phase C2: softmax + argmax + hid (pair of blocks per batch) ----
        {
            int b = blk >> 1, half = blk & 1;
            if (tid < LL) {
                sm_sc[tid] = __ldcg(&g_sc[b * LL + tid]);
                sm_mask[tid] = g_mask[b * LL + tid];
            }
            __syncthreads();

            if (w == 0) {
                float sv[4], mk[4];
#pragma unroll
                for (int j = 0; j < 4; j++) {
                    mk[j] = sm_mask[lane + 32 * j];
                    sv[j] = (mk[j] != 0.f) ? sm_sc[lane + 32 * j] : -3.4e38f;
                }
                float m = fmaxf(fmaxf(sv[0], sv[1]), fmaxf(sv[2], sv[3]));
#pragma unroll
                for (int off = 16; off; off >>= 1)
                    m = fmaxf(m, __shfl_xor_sync(0xffffffffu, m, off));

                float e[4], sum = 0.f;
#pragma unroll
                for (int j = 0; j < 4; j++) {
                    e[j] = (mk[j] != 0.f) ? expf(sv[j] - m) : 0.f;
                    sum += e[j];
                }
                sum = wsum(sum);
                float inv = 1.f / sum;

                float best = -1.f;
                int bidx = 0;
#pragma unroll
                for (int j = 0; j < 4; j++) {
                    int l = lane + 32 * j;
                    float a = e[j] * inv;
                    sm_alpha[l] = a;
                    if (half == 0)
                        out[(size_t)b * LL * LL + (size_t)t * LL + l] = a;
                    float cand = (mk[j] != 0.f) ? a : -1.f;
                    if (cand > best) { best = cand; bidx = l; }
                }
#pragma unroll
                for (int off = 16; off; off >>= 1) {
                    float ob = __shfl_xor_sync(0xffffffffu, best, off);
                    int oi = __shfl_xor_sync(0xffffffffu, bidx, off);
                    if (ob > best || (ob == best && oi < bidx)) { best = ob; bidx = oi; }
                }
                if (half == 0 && lane == 0) {
                    out[OUT_PTR + b * LL + t] = (float)bidx;
                    g_bidx[b] = bidx;
                }
            }
            __syncthreads();

            {
                int lh = tid >> 8;
                int hh = half * 256 + (tid & 255);
                const float* cp = g_ctx + (size_t)b * LL * HH + (size_t)(lh * 64) * HH + hh;
                float a = 0.f;
#pragma unroll 8
                for (int l = 0; l < 64; l++)
                    a += __ldcg(cp + (size_t)l * HH) * sm_alpha[lh * 64 + l];
                sm_part[tid] = a;
            }
            __syncthreads();
            if (tid < 256)
                g_cat[b * 2 * HH + half * 256 + tid] = sm_part[tid] + sm_part[256 + tid];
        }
        gbar(++ep);

        // ---- Phase D: h = tanh(W_out * [hid, h_t] + b_out) + mask update ----
        {
            if (blk == 0 && tid < BB)
                g_mask[tid * LL + g_bidx[tid]] = 0.f;

            int rt = blk & 15, bt = blk >> 4;
            int bbase = bt * 8, r0 = rt * 32 + w * 2;
            {
                const float4* src = (const float4*)(g_cat + (size_t)bbase * 2 * HH);
                float4* dst = (float4*)xs;
                for (int idx = tid; idx < 8 * 1024 / 4; idx += TPB)
                    dst[idx] = __ldcg(src + idx);
            }
            __syncthreads();

            const float* w0 = Wout + (size_t)r0 * 2 * HH;
            const float* w1 = Wout + (size_t)(r0 + 1) * 2 * HH;
            float2 acc[2][8];
#pragma unroll
            for (int r = 0; r < 2; r++)
#pragma unroll
                for (int b = 0; b < 8; b++) acc[r][b] = make_float2(0.f, 0.f);

            float2 a0 = *(const float2*)(w0 + lane * 2);
            float2 a1 = *(const float2*)(w1 + lane * 2);
#pragma unroll
            for (int kk = 0; kk < 16; kk++) {
                float2 na0, na1;
                if (kk < 15) {
                    int kn = (kk + 1) * 64 + lane * 2;
                    na0 = *(const float2*)(w0 + kn);
                    na1 = *(const float2*)(w1 + kn);
                }
                int k = kk * 64 + lane * 2;
#pragma unroll
                for (int b = 0; b < 8; b++) {
                    float2 xv = *(const float2*)&xs[b * 1024 + k];
                    ffma2(acc[0][b], a0, xv);
                    ffma2(acc[1][b], a1, xv);
                }
                if (kk < 15) { a0 = na0; a1 = na1; }
            }

            float res[2] = {0.f, 0.f};
#pragma unroll
            for (int r = 0; r < 2; r++)
#pragma unroll
                for (int b = 0; b < 8; b++) {
                    float vv = wsum(acc[r][b].x + acc[r][b].y);
                    if (lane == b) res[r] = vv;
                }
            if (lane < 8) {
#pragma unroll
                for (int r = 0; r < 2; r++)
                    g_h[(size_t)(bbase + lane) * HH + r0 + r] =
                        tanhf(res[r] + bout[r0 + r]);
            }
        }
        gbar(++ep);
    }

    // final h/c copy (g_h/g_c visible after last gbar)
    for (int i = blk * TPB + tid; i < BB * HH; i += GRID * TPB) {
        out[OUT_H + i] = g_h[i];
        out[OUT_C + i] = g_c[i];
    }
    // no flag reset: epochs persist; next call reads g_rel as base
}

extern "C" void kernel_launch(void* const* d_in, const int* in_sizes, int n_in,
                              void* d_out, int out_size) {
    const float* h0   = (const float*)d_in[2];
    const float* c0   = (const float*)d_in[3];
    const float* ctxi = (const float*)d_in[4];
    const float* Whh  = (const float*)d_in[5];
    const float* bhh  = (const float*)d_in[6];
    const float* Win  = (const float*)d_in[7];
    const float* bin  = (const float*)d_in[8];
    const float* Wc   = (const float*)d_in[9];
    const float* bc   = (const float*)d_in[10];
    const float* V    = (const float*)d_in[11];
    const float* Wout = (const float*)d_in[12];
    const float* bout = (const float*)d_in[13];
    float* out = (float*)d_out;

    k_all<<<GRID, TPB>>>(h0, c0, ctxi, Wc, bc, Whh, bhh,
                         Win, bin, Wout, bout, V, out);
}